// round 4
// baseline (speedup 1.0000x reference)
#include <cuda_runtime.h>
#include <cuda_bf16.h>
#include <cstdint>

#define NN 100000
#define NE 3200000
#define NG 64
#define F1 128
#define F2 256

// ---------------- device scratch (no allocation allowed) ----------------
__device__ int   g_is64;
__device__ int   g_src[NE];
__device__ int   g_dst[NE];
__device__ int   g_batch[NN];
__device__ float g_deg[NN];
__device__ float g_dinv[NN];
__device__ float g_norm[NE];
__device__ float g_agg1[(size_t)NN * F1];
__device__ float g_h1[(size_t)NN * F2];
__device__ float g_agg2[(size_t)NN * F2];
__device__ float g_h2[(size_t)NN * F2];
__device__ float g_pool[NG * F2];
__device__ float g_cnt[NG];

// vectorized global reduction (sm_90+)
__device__ __forceinline__ void red_add_v4(float* p, float a, float b, float c, float d) {
    asm volatile("red.global.add.v4.f32 [%0], {%1,%2,%3,%4};"
                 :: "l"(p), "f"(a), "f"(b), "f"(c), "f"(d) : "memory");
}

// ---------------- dtype detection (int64 vs int32 edge_index) ----------------
__global__ void detect_kernel(const unsigned int* __restrict__ w) {
    if (blockIdx.x == 0 && threadIdx.x == 0) {
        int is64 = 1;
        for (int i = 0; i < 256; i++) {
            if (w[2 * i + 1] != 0u) { is64 = 0; break; }
        }
        g_is64 = is64;
    }
}

// normalize indices into int32 scratch; zero accumulators
__global__ void prep_kernel(const void* __restrict__ ei, const void* __restrict__ batch) {
    long long i = (long long)blockIdx.x * blockDim.x + threadIdx.x;
    int is64 = g_is64;
    if (i < NE) {
        if (is64) {
            const long long* p = (const long long*)ei;
            g_src[i] = (int)p[i];
            g_dst[i] = (int)p[(long long)NE + i];
        } else {
            const int* p = (const int*)ei;
            g_src[i] = p[i];
            g_dst[i] = p[NE + i];
        }
    }
    if (i < NN) {
        g_deg[i] = 0.0f;
        if (is64) g_batch[i] = (int)((const long long*)batch)[i];
        else      g_batch[i] = ((const int*)batch)[i];
    }
    if (i < NG * F2) g_pool[i] = 0.0f;
    if (i < NG)      g_cnt[i]  = 0.0f;
}

__global__ void deg_kernel() {
    long long i = (long long)blockIdx.x * blockDim.x + threadIdx.x;
    if (i < NE) atomicAdd(&g_deg[g_dst[i]], 1.0f);
}

__global__ void dinv_kernel() {
    long long i = (long long)blockIdx.x * blockDim.x + threadIdx.x;
    if (i < NN) g_dinv[i] = rsqrtf(g_deg[i] + 1.0f);  // +1 self loop; deg>=1 always
}

__global__ void norm_kernel() {
    long long i = (long long)blockIdx.x * blockDim.x + threadIdx.x;
    if (i < NE) g_norm[i] = g_dinv[g_src[i]] * g_dinv[g_dst[i]];
}

// self-loop init: out[v] = dinv[v]^2 * h[v]   (overwrites, no pre-zero needed)
__global__ void self1_kernel(const float* __restrict__ x) {
    const int CH = F1 / 4;
    long long i = (long long)blockIdx.x * blockDim.x + threadIdx.x;
    if (i >= (long long)NN * CH) return;
    int v = (int)(i >> 5);   // i / 32
    float s = g_dinv[v]; s = s * s;
    float4 val = ((const float4*)x)[i];
    float4 o = {val.x * s, val.y * s, val.z * s, val.w * s};
    ((float4*)g_agg1)[i] = o;
}

__global__ void self2_kernel() {
    const int CH = F2 / 4;
    long long i = (long long)blockIdx.x * blockDim.x + threadIdx.x;
    if (i >= (long long)NN * CH) return;
    int v = (int)(i >> 6);   // i / 64
    float s = g_dinv[v]; s = s * s;
    float4 val = ((const float4*)g_h1)[i];
    float4 o = {val.x * s, val.y * s, val.z * s, val.w * s};
    ((float4*)g_agg2)[i] = o;
}

// edge-parallel scatter: agg[dst] += norm * h[src]
__global__ void edge_agg1_kernel(const float* __restrict__ x) {
    const int CH = F1 / 4;  // 32
    long long i = (long long)blockIdx.x * blockDim.x + threadIdx.x;
    if (i >= (long long)NE * CH) return;
    int e = (int)(i >> 5);
    int c = (int)(i & 31);
    int s = g_src[e], d = g_dst[e];
    float nrm = g_norm[e];
    float4 v = ((const float4*)x)[(long long)s * CH + c];
    red_add_v4(g_agg1 + (long long)d * F1 + c * 4, v.x * nrm, v.y * nrm, v.z * nrm, v.w * nrm);
}

__global__ void edge_agg2_kernel() {
    const int CH = F2 / 4;  // 64
    long long i = (long long)blockIdx.x * blockDim.x + threadIdx.x;
    if (i >= (long long)NE * CH) return;
    int e = (int)(i >> 6);
    int c = (int)(i & 63);
    int s = g_src[e], d = g_dst[e];
    float nrm = g_norm[e];
    float4 v = ((const float4*)g_h1)[(long long)s * CH + c];
    red_add_v4(g_agg2 + (long long)d * F2 + c * 4, v.x * nrm, v.y * nrm, v.z * nrm, v.w * nrm);
}

// ---------------- fp32 SGEMM: C = relu(A[M,K] @ B[K,N] + bias) ----------------
// layer==1: A=g_agg1, C=g_h1 ; layer==2: A=g_agg2, C=g_h2
__global__ __launch_bounds__(256) void sgemm_bias_relu(
    const float* __restrict__ B, const float* __restrict__ bias,
    int M, int N, int K, int layer)
{
    const int BM = 128, BN = 128, BK = 16, TM = 8, TN = 8;
    const float* __restrict__ A = (layer == 1) ? g_agg1 : g_agg2;
    float* __restrict__ C       = (layer == 1) ? g_h1   : g_h2;

    __shared__ float As[BK][BM];
    __shared__ float Bs[BK][BN];

    int tid = threadIdx.x;
    int block_row = blockIdx.y * BM;
    int block_col = blockIdx.x * BN;

    int aRow = tid >> 2;          // 0..63
    int aCol = (tid & 3) * 4;     // 0,4,8,12
    int bRow = tid >> 5;          // 0..7
    int bCol = (tid & 31) * 4;    // 0..124

    int tx = tid & 15, ty = tid >> 4;

    float acc[TM][TN];
#pragma unroll
    for (int i = 0; i < TM; i++)
#pragma unroll
        for (int j = 0; j < TN; j++) acc[i][j] = 0.0f;

    for (int k0 = 0; k0 < K; k0 += BK) {
#pragma unroll
        for (int p = 0; p < 2; ++p) {
            int r = block_row + aRow + p * 64;
            float4 v = make_float4(0.f, 0.f, 0.f, 0.f);
            if (r < M) v = *(const float4*)(A + (size_t)r * K + k0 + aCol);
            As[aCol + 0][aRow + p * 64] = v.x;
            As[aCol + 1][aRow + p * 64] = v.y;
            As[aCol + 2][aRow + p * 64] = v.z;
            As[aCol + 3][aRow + p * 64] = v.w;
        }
#pragma unroll
        for (int p = 0; p < 2; ++p) {
            int r = k0 + bRow + p * 8;
            *(float4*)&Bs[bRow + p * 8][bCol] =
                *(const float4*)(B + (size_t)r * N + block_col + bCol);
        }
        __syncthreads();

#pragma unroll
        for (int kk = 0; kk < BK; ++kk) {
            float a[TM], b[TN];
#pragma unroll
            for (int i = 0; i < TM; i++) a[i] = As[kk][ty * TM + i];
#pragma unroll
            for (int j = 0; j < TN; j++) b[j] = Bs[kk][tx * TN + j];
#pragma unroll
            for (int i = 0; i < TM; i++)
#pragma unroll
                for (int j = 0; j < TN; j++) acc[i][j] = fmaf(a[i], b[j], acc[i][j]);
        }
        __syncthreads();
    }

#pragma unroll
    for (int i = 0; i < TM; i++) {
        int r = block_row + ty * TM + i;
        if (r >= M) break;
#pragma unroll
        for (int j = 0; j < TN; j += 4) {
            int c = block_col + tx * TN + j;
            float4 o;
            o.x = fmaxf(acc[i][j + 0] + bias[c + 0], 0.0f);
            o.y = fmaxf(acc[i][j + 1] + bias[c + 1], 0.0f);
            o.z = fmaxf(acc[i][j + 2] + bias[c + 2], 0.0f);
            o.w = fmaxf(acc[i][j + 3] + bias[c + 3], 0.0f);
            *(float4*)(C + (size_t)r * N + c) = o;
        }
    }
}

// ---------------- pooling: pooled[g] += h2[v], cnt[g] += 1 ----------------
__global__ void pool_kernel() {
    const int CH = F2 / 4;  // 64
    long long i = (long long)blockIdx.x * blockDim.x + threadIdx.x;
    if (i >= (long long)NN * CH) return;
    int v = (int)(i >> 6);
    int c = (int)(i & 63);
    int g = g_batch[v];
    float4 val = ((const float4*)g_h2)[i];
    red_add_v4(g_pool + (long long)g * F2 + c * 4, val.x, val.y, val.z, val.w);
    if (c == 0) atomicAdd(&g_cnt[g], 1.0f);
}

// ---------------- head: logits + log_softmax ----------------
__global__ void final_kernel(const float* __restrict__ fcw, const float* __restrict__ fcb,
                             float* __restrict__ out) {
    int g = threadIdx.x;
    if (g >= NG) return;
    float inv = 1.0f / fmaxf(g_cnt[g], 1.0f);
    float l0 = fcb[0], l1 = fcb[1];
    const float* p = g_pool + g * F2;
#pragma unroll 8
    for (int k = 0; k < F2; k++) {
        float pv = p[k] * inv;
        l0 = fmaf(pv, fcw[k * 2 + 0], l0);
        l1 = fmaf(pv, fcw[k * 2 + 1], l1);
    }
    float m = fmaxf(l0, l1);
    float lse = m + logf(expf(l0 - m) + expf(l1 - m));
    out[g * 2 + 0] = l0 - lse;
    out[g * 2 + 1] = l1 - lse;
}

// ---------------- launch ----------------
extern "C" void kernel_launch(void* const* d_in, const int* in_sizes, int n_in,
                              void* d_out, int out_size) {
    const float* x    = (const float*)d_in[0];
    const void*  ei   = d_in[1];
    const void*  batc = d_in[2];
    const float* W1   = (const float*)d_in[3];
    const float* b1   = (const float*)d_in[4];
    const float* W2   = (const float*)d_in[5];
    const float* b2   = (const float*)d_in[6];
    const float* fcw  = (const float*)d_in[7];
    const float* fcb  = (const float*)d_in[8];
    float* out = (float*)d_out;

    const int T = 256;
    detect_kernel<<<1, 32>>>((const unsigned int*)ei);
    prep_kernel<<<(NE + T - 1) / T, T>>>(ei, batc);
    deg_kernel<<<(NE + T - 1) / T, T>>>();
    dinv_kernel<<<(NN + T - 1) / T, T>>>();
    norm_kernel<<<(NE + T - 1) / T, T>>>();

    // layer 1: aggregate x (128-wide) then GEMM with W1
    {
        long long tot = (long long)NN * (F1 / 4);
        self1_kernel<<<(unsigned)((tot + T - 1) / T), T>>>(x);
        long long tote = (long long)NE * (F1 / 4);
        edge_agg1_kernel<<<(unsigned)((tote + T - 1) / T), T>>>(x);
        dim3 grid(F2 / 128, (NN + 127) / 128);
        sgemm_bias_relu<<<grid, 256>>>(W1, b1, NN, F2, F1, 1);
    }
    // layer 2: aggregate h1 (256-wide) then GEMM with W2
    {
        long long tot = (long long)NN * (F2 / 4);
        self2_kernel<<<(unsigned)((tot + T - 1) / T), T>>>();
        long long tote = (long long)NE * (F2 / 4);
        edge_agg2_kernel<<<(unsigned)((tote + T - 1) / T), T>>>();
        dim3 grid(F2 / 128, (NN + 127) / 128);
        sgemm_bias_relu<<<grid, 256>>>(W2, b2, NN, F2, F2, 2);
    }
    // pool + head
    {
        long long tot = (long long)NN * (F2 / 4);
        pool_kernel<<<(unsigned)((tot + T - 1) / T), T>>>();
        final_kernel<<<1, 64>>>(fcw, fcb, out);
    }
}

// round 5
// speedup vs baseline: 1.9031x; 1.9031x over previous
#include <cuda_runtime.h>
#include <cuda_bf16.h>
#include <cstdint>

#define NN 100000
#define NE 3200000
#define NG 64
#define F1 128
#define F2 256
#define SCAN_B 256
#define NB ((NN + SCAN_B - 1) / SCAN_B)   // 391

// ---------------- device scratch (no allocation allowed) ----------------
__device__ int   g_is64;
__device__ int   g_src[NE];
__device__ int   g_dst[NE];
__device__ int   g_csrc[NE];          // dst-sorted src indices (CSR col array)
__device__ int   g_rowptr[NN + 1];
__device__ int   g_degc[NN];
__device__ int   g_cur[NN];
__device__ int   g_bsum[NB];
__device__ int   g_boff[NB];
__device__ int   g_batch[NN];
__device__ float g_dinv[NN];
__device__ float g_agg1[(size_t)NN * F1];
__device__ float g_h1[(size_t)NN * F2];
__device__ float g_agg2[(size_t)NN * F2];
__device__ float g_h2[(size_t)NN * F2];
__device__ float g_pool[NG * F2];
__device__ float g_cnt[NG];

__device__ __forceinline__ void red_add_v4(float* p, float a, float b, float c, float d) {
    asm volatile("red.global.add.v4.f32 [%0], {%1,%2,%3,%4};"
                 :: "l"(p), "f"(a), "f"(b), "f"(c), "f"(d) : "memory");
}

// ---------------- dtype detection (int64 vs int32 edge_index) ----------------
__global__ void detect_kernel(const unsigned int* __restrict__ w) {
    if (blockIdx.x == 0 && threadIdx.x == 0) {
        int is64 = 1;
        for (int i = 0; i < 256; i++)
            if (w[2 * i + 1] != 0u) { is64 = 0; break; }
        g_is64 = is64;
    }
}

// normalize indices to int32; zero counters
__global__ void prep_kernel(const void* __restrict__ ei, const void* __restrict__ batch) {
    long long i = (long long)blockIdx.x * blockDim.x + threadIdx.x;
    int is64 = g_is64;
    if (i < NE) {
        if (is64) {
            const long long* p = (const long long*)ei;
            g_src[i] = (int)p[i];
            g_dst[i] = (int)p[(long long)NE + i];
        } else {
            const int* p = (const int*)ei;
            g_src[i] = p[i];
            g_dst[i] = p[NE + i];
        }
    }
    if (i < NN) {
        g_degc[i] = 0;
        g_cur[i]  = 0;
        if (is64) g_batch[i] = (int)((const long long*)batch)[i];
        else      g_batch[i] = ((const int*)batch)[i];
    }
    if (i < NG * F2) g_pool[i] = 0.0f;
    if (i < NG)      g_cnt[i]  = 0.0f;
}

// ---------------- CSR build ----------------
__global__ void hist_kernel() {
    long long i = (long long)blockIdx.x * blockDim.x + threadIdx.x;
    if (i < NE) atomicAdd(&g_degc[g_dst[i]], 1);
}

__global__ void scan_block_kernel() {
    __shared__ int sh[SCAN_B];
    int t = threadIdx.x;
    int i = blockIdx.x * SCAN_B + t;
    int v = (i < NN) ? g_degc[i] : 0;
    sh[t] = v;
    __syncthreads();
#pragma unroll
    for (int off = 1; off < SCAN_B; off <<= 1) {
        int add = (t >= off) ? sh[t - off] : 0;
        __syncthreads();
        sh[t] += add;
        __syncthreads();
    }
    if (i < NN) g_rowptr[i] = sh[t] - v;   // exclusive within block
    if (t == SCAN_B - 1) g_bsum[blockIdx.x] = sh[t];
}

__global__ void scan_top_kernel() {
    if (threadIdx.x == 0) {
        int run = 0;
        for (int b = 0; b < NB; b++) { g_boff[b] = run; run += g_bsum[b]; }
        g_rowptr[NN] = run;   // == NE
    }
}

__global__ void scan_add_kernel() {
    long long i = (long long)blockIdx.x * blockDim.x + threadIdx.x;
    if (i < NN) g_rowptr[i] += g_boff[i >> 8];
}

__global__ void dinv_kernel() {
    long long i = (long long)blockIdx.x * blockDim.x + threadIdx.x;
    if (i < NN) g_dinv[i] = rsqrtf((float)g_degc[i] + 1.0f);  // +1 self loop
}

__global__ void scatter_kernel() {
    long long i = (long long)blockIdx.x * blockDim.x + threadIdx.x;
    if (i < NE) {
        int d = g_dst[i];
        int pos = g_rowptr[d] + atomicAdd(&g_cur[d], 1);
        g_csrc[pos] = g_src[i];
    }
}

// ---------------- CSR aggregation: one warp per node ----------------
// agg[d] = dinv[d] * sum_e dinv[src_e]*h[src_e]  +  dinv[d]^2 * h[d]
__global__ __launch_bounds__(256) void agg1_csr(const float* __restrict__ x) {
    int node = blockIdx.x * 8 + (threadIdx.x >> 5);
    if (node >= NN) return;
    int lane = threadIdx.x & 31;
    int beg = g_rowptr[node], end = g_rowptr[node + 1];
    float4 acc = {0.f, 0.f, 0.f, 0.f};
    int e = beg;
    for (; e + 4 <= end; e += 4) {
        int s0 = g_csrc[e], s1 = g_csrc[e + 1], s2 = g_csrc[e + 2], s3 = g_csrc[e + 3];
        float w0 = g_dinv[s0], w1 = g_dinv[s1], w2 = g_dinv[s2], w3 = g_dinv[s3];
        float4 v0 = ((const float4*)x)[(size_t)s0 * 32 + lane];
        float4 v1 = ((const float4*)x)[(size_t)s1 * 32 + lane];
        float4 v2 = ((const float4*)x)[(size_t)s2 * 32 + lane];
        float4 v3 = ((const float4*)x)[(size_t)s3 * 32 + lane];
        acc.x += w0 * v0.x + w1 * v1.x + w2 * v2.x + w3 * v3.x;
        acc.y += w0 * v0.y + w1 * v1.y + w2 * v2.y + w3 * v3.y;
        acc.z += w0 * v0.z + w1 * v1.z + w2 * v2.z + w3 * v3.z;
        acc.w += w0 * v0.w + w1 * v1.w + w2 * v2.w + w3 * v3.w;
    }
    for (; e < end; e++) {
        int s = g_csrc[e];
        float w = g_dinv[s];
        float4 v = ((const float4*)x)[(size_t)s * 32 + lane];
        acc.x += w * v.x; acc.y += w * v.y; acc.z += w * v.z; acc.w += w * v.w;
    }
    float di = g_dinv[node];
    float4 self = ((const float4*)x)[(size_t)node * 32 + lane];
    float4 o;
    o.x = di * acc.x + di * di * self.x;
    o.y = di * acc.y + di * di * self.y;
    o.z = di * acc.z + di * di * self.z;
    o.w = di * acc.w + di * di * self.w;
    ((float4*)g_agg1)[(size_t)node * 32 + lane] = o;
}

__global__ __launch_bounds__(256) void agg2_csr() {
    int node = blockIdx.x * 8 + (threadIdx.x >> 5);
    if (node >= NN) return;
    int lane = threadIdx.x & 31;
    int beg = g_rowptr[node], end = g_rowptr[node + 1];
    float4 accA = {0.f, 0.f, 0.f, 0.f};
    float4 accB = {0.f, 0.f, 0.f, 0.f};
    const float4* h1 = (const float4*)g_h1;
    int e = beg;
    for (; e + 2 <= end; e += 2) {
        int s0 = g_csrc[e], s1 = g_csrc[e + 1];
        float w0 = g_dinv[s0], w1 = g_dinv[s1];
        float4 a0 = h1[(size_t)s0 * 64 + lane];
        float4 b0 = h1[(size_t)s0 * 64 + 32 + lane];
        float4 a1 = h1[(size_t)s1 * 64 + lane];
        float4 b1 = h1[(size_t)s1 * 64 + 32 + lane];
        accA.x += w0 * a0.x + w1 * a1.x;  accA.y += w0 * a0.y + w1 * a1.y;
        accA.z += w0 * a0.z + w1 * a1.z;  accA.w += w0 * a0.w + w1 * a1.w;
        accB.x += w0 * b0.x + w1 * b1.x;  accB.y += w0 * b0.y + w1 * b1.y;
        accB.z += w0 * b0.z + w1 * b1.z;  accB.w += w0 * b0.w + w1 * b1.w;
    }
    for (; e < end; e++) {
        int s = g_csrc[e];
        float w = g_dinv[s];
        float4 a = h1[(size_t)s * 64 + lane];
        float4 b = h1[(size_t)s * 64 + 32 + lane];
        accA.x += w * a.x; accA.y += w * a.y; accA.z += w * a.z; accA.w += w * a.w;
        accB.x += w * b.x; accB.y += w * b.y; accB.z += w * b.z; accB.w += w * b.w;
    }
    float di = g_dinv[node];
    float di2 = di * di;
    float4 sa = h1[(size_t)node * 64 + lane];
    float4 sb = h1[(size_t)node * 64 + 32 + lane];
    float4 oa, ob;
    oa.x = di * accA.x + di2 * sa.x;  oa.y = di * accA.y + di2 * sa.y;
    oa.z = di * accA.z + di2 * sa.z;  oa.w = di * accA.w + di2 * sa.w;
    ob.x = di * accB.x + di2 * sb.x;  ob.y = di * accB.y + di2 * sb.y;
    ob.z = di * accB.z + di2 * sb.z;  ob.w = di * accB.w + di2 * sb.w;
    ((float4*)g_agg2)[(size_t)node * 64 + lane] = oa;
    ((float4*)g_agg2)[(size_t)node * 64 + 32 + lane] = ob;
}

// ---------------- fp32 SGEMM: C = relu(A[M,K] @ B[K,N] + bias) ----------------
__global__ __launch_bounds__(256) void sgemm_bias_relu(
    const float* __restrict__ B, const float* __restrict__ bias,
    int M, int N, int K, int layer)
{
    const int BM = 128, BN = 128, BK = 16, TM = 8, TN = 8;
    const float* __restrict__ A = (layer == 1) ? g_agg1 : g_agg2;
    float* __restrict__ C       = (layer == 1) ? g_h1   : g_h2;

    __shared__ float As[BK][BM];
    __shared__ float Bs[BK][BN];

    int tid = threadIdx.x;
    int block_row = blockIdx.y * BM;
    int block_col = blockIdx.x * BN;

    int aRow = tid >> 2;
    int aCol = (tid & 3) * 4;
    int bRow = tid >> 5;
    int bCol = (tid & 31) * 4;
    int tx = tid & 15, ty = tid >> 4;

    float acc[TM][TN];
#pragma unroll
    for (int i = 0; i < TM; i++)
#pragma unroll
        for (int j = 0; j < TN; j++) acc[i][j] = 0.0f;

    for (int k0 = 0; k0 < K; k0 += BK) {
#pragma unroll
        for (int p = 0; p < 2; ++p) {
            int r = block_row + aRow + p * 64;
            float4 v = make_float4(0.f, 0.f, 0.f, 0.f);
            if (r < M) v = *(const float4*)(A + (size_t)r * K + k0 + aCol);
            As[aCol + 0][aRow + p * 64] = v.x;
            As[aCol + 1][aRow + p * 64] = v.y;
            As[aCol + 2][aRow + p * 64] = v.z;
            As[aCol + 3][aRow + p * 64] = v.w;
        }
#pragma unroll
        for (int p = 0; p < 2; ++p) {
            int r = k0 + bRow + p * 8;
            *(float4*)&Bs[bRow + p * 8][bCol] =
                *(const float4*)(B + (size_t)r * N + block_col + bCol);
        }
        __syncthreads();

#pragma unroll
        for (int kk = 0; kk < BK; ++kk) {
            float a[TM], b[TN];
#pragma unroll
            for (int i = 0; i < TM; i++) a[i] = As[kk][ty * TM + i];
#pragma unroll
            for (int j = 0; j < TN; j++) b[j] = Bs[kk][tx * TN + j];
#pragma unroll
            for (int i = 0; i < TM; i++)
#pragma unroll
                for (int j = 0; j < TN; j++) acc[i][j] = fmaf(a[i], b[j], acc[i][j]);
        }
        __syncthreads();
    }

#pragma unroll
    for (int i = 0; i < TM; i++) {
        int r = block_row + ty * TM + i;
        if (r >= M) break;
#pragma unroll
        for (int j = 0; j < TN; j += 4) {
            int c = block_col + tx * TN + j;
            float4 o;
            o.x = fmaxf(acc[i][j + 0] + bias[c + 0], 0.0f);
            o.y = fmaxf(acc[i][j + 1] + bias[c + 1], 0.0f);
            o.z = fmaxf(acc[i][j + 2] + bias[c + 2], 0.0f);
            o.w = fmaxf(acc[i][j + 3] + bias[c + 3], 0.0f);
            *(float4*)(C + (size_t)r * N + c) = o;
        }
    }
}

// ---------------- pooling ----------------
__global__ void pool_kernel() {
    const int CH = F2 / 4;
    long long i = (long long)blockIdx.x * blockDim.x + threadIdx.x;
    if (i >= (long long)NN * CH) return;
    int v = (int)(i >> 6);
    int c = (int)(i & 63);
    int g = g_batch[v];
    float4 val = ((const float4*)g_h2)[i];
    red_add_v4(g_pool + (long long)g * F2 + c * 4, val.x, val.y, val.z, val.w);
    if (c == 0) atomicAdd(&g_cnt[g], 1.0f);
}

// ---------------- head ----------------
__global__ void final_kernel(const float* __restrict__ fcw, const float* __restrict__ fcb,
                             float* __restrict__ out) {
    int g = threadIdx.x;
    if (g >= NG) return;
    float inv = 1.0f / fmaxf(g_cnt[g], 1.0f);
    float l0 = fcb[0], l1 = fcb[1];
    const float* p = g_pool + g * F2;
#pragma unroll 8
    for (int k = 0; k < F2; k++) {
        float pv = p[k] * inv;
        l0 = fmaf(pv, fcw[k * 2 + 0], l0);
        l1 = fmaf(pv, fcw[k * 2 + 1], l1);
    }
    float m = fmaxf(l0, l1);
    float lse = m + logf(expf(l0 - m) + expf(l1 - m));
    out[g * 2 + 0] = l0 - lse;
    out[g * 2 + 1] = l1 - lse;
}

// ---------------- launch ----------------
extern "C" void kernel_launch(void* const* d_in, const int* in_sizes, int n_in,
                              void* d_out, int out_size) {
    const float* x    = (const float*)d_in[0];
    const void*  ei   = d_in[1];
    const void*  batc = d_in[2];
    const float* W1   = (const float*)d_in[3];
    const float* b1   = (const float*)d_in[4];
    const float* W2   = (const float*)d_in[5];
    const float* b2   = (const float*)d_in[6];
    const float* fcw  = (const float*)d_in[7];
    const float* fcb  = (const float*)d_in[8];
    float* out = (float*)d_out;

    const int T = 256;
    detect_kernel<<<1, 32>>>((const unsigned int*)ei);
    prep_kernel<<<(NE + T - 1) / T, T>>>(ei, batc);
    hist_kernel<<<(NE + T - 1) / T, T>>>();
    scan_block_kernel<<<NB, SCAN_B>>>();
    scan_top_kernel<<<1, 1>>>();
    scan_add_kernel<<<(NN + T - 1) / T, T>>>();
    dinv_kernel<<<(NN + T - 1) / T, T>>>();
    scatter_kernel<<<(NE + T - 1) / T, T>>>();

    // layer 1
    agg1_csr<<<(NN + 7) / 8, 256>>>(x);
    {
        dim3 grid(F2 / 128, (NN + 127) / 128);
        sgemm_bias_relu<<<grid, 256>>>(W1, b1, NN, F2, F1, 1);
    }
    // layer 2
    agg2_csr<<<(NN + 7) / 8, 256>>>();
    {
        dim3 grid(F2 / 128, (NN + 127) / 128);
        sgemm_bias_relu<<<grid, 256>>>(W2, b2, NN, F2, F2, 2);
    }
    // pool + head
    {
        long long tot = (long long)NN * (F2 / 4);
        pool_kernel<<<(unsigned)((tot + T - 1) / T), T>>>();
        final_kernel<<<1, 64>>>(fcw, fcb, out);
    }
}